// round 16
// baseline (speedup 1.0000x reference)
#include <cuda_runtime.h>
#include <cuda_fp16.h>
#include <cstdint>

#define BATCH   8192
#define INF     1024
#define LEAFW   256
#define OUTF    1024
#define NLEAF   16
#define NNODE   15
#define ACOLS   4096
#define APITCH  4160      // ACOLS + 16 mix + 48 zero pad (divisible by 64)

// Scratch (device globals; allocation-free rule)
__device__ float  g_logits[BATCH * 16];
__device__ float  g_mix[BATCH * 16];
__device__ float  g_b1c[ACOLS];                     // b1 in physical col order
__device__ __half g_xc [(size_t)BATCH * INF];       // fp16, k-permuted x
__device__ __half g_w1c[(size_t)ACOLS * INF];       // W1^T [n_phys][k_phys] fp16
__device__ __half g_w2c[(size_t)OUTF * APITCH];     // [W2;b2;0]^T [o][k_phys] fp16
__device__ __half g_A  [(size_t)BATCH * APITCH];    // GEMM1 out (phys cols) + mix cols

// involution on k within 32-blocks: lane c's mma-k set {2c,2c+1,2c+8,2c+9,(+16)}
// becomes contiguous: phys = 8*((k>>1)&3) + 2*((k>>3)&3) + (k&1)
__device__ __forceinline__ int p32(int k) {
    return (k & ~31) | ((((k >> 1) & 3) << 3) | (((k >> 3) & 3) << 1) | (k & 1));
}
// pair-level view of p32 (phys pair j holds logical pair pairperm(j)); involution
__device__ __forceinline__ int pairperm(int j) {
    return (j & ~15) | ((j & 3) << 2) | ((j >> 2) & 3);
}

__device__ __forceinline__ void mma_f16(float c[4], unsigned a0, unsigned a1,
                                        unsigned a2, unsigned a3,
                                        unsigned b0, unsigned b1) {
    asm volatile(
        "mma.sync.aligned.m16n8k16.row.col.f32.f16.f16.f32 "
        "{%0,%1,%2,%3}, {%4,%5,%6,%7}, {%8,%9}, {%0,%1,%2,%3};\n"
        : "+f"(c[0]), "+f"(c[1]), "+f"(c[2]), "+f"(c[3])
        : "r"(a0), "r"(a1), "r"(a2), "r"(a3), "r"(b0), "r"(b1));
}

__device__ __forceinline__ void cpasync16(const void* dst, const void* src) {
    unsigned d = (unsigned)__cvta_generic_to_shared(dst);
    asm volatile("cp.async.cg.shared.global [%0], [%1], 16;\n" :: "r"(d), "l"(src));
}

// ---------------------------------------------------------------------------
// Fused prep A: blocks [0,16384) convert x; blocks [16384,20480) pack W1.
// ---------------------------------------------------------------------------
__global__ void k_prep_a(const float* __restrict__ x,
                         const float* __restrict__ w1s) {
    __shared__ float ts[32][33];
    int tid = threadIdx.x;
    if (blockIdx.x < 16384) {
        int idx = blockIdx.x * 256 + tid;          // phys half2-pair id (4M)
        int m = idx >> 9;                          // 512 pairs per row
        int j = idx & 511;
        int lj = pairperm(j);                      // logical pair
        float2 v = *(const float2*)(x + (size_t)m * INF + 2 * lj);
        ((half2*)g_xc)[(size_t)m * 512 + j] = __floats2half2_rn(v.x, v.y);
    } else {
        int bid = blockIdx.x - 16384;
        int l  = bid >> 8;
        int f0 = ((bid >> 3) & 31) * 32;
        int h0 = (bid & 7) * 32;
        int fi = tid >> 3, hj = (tid & 7) * 4;
        float4 v = *(const float4*)(w1s + ((size_t)l * INF + f0 + fi) * LEAFW + h0 + hj);
        ts[hj + 0][fi] = v.x; ts[hj + 1][fi] = v.y;
        ts[hj + 2][fi] = v.z; ts[hj + 3][fi] = v.w;
        __syncthreads();
        int hi = tid >> 3, fj = (tid & 7) * 4;
        size_t drow = (size_t)p32(l * LEAFW + h0 + hi) * INF;
#pragma unroll
        for (int e = 0; e < 4; e++)
            g_w1c[drow + p32(f0 + fj + e)] = __float2half(ts[hi][fj + e]);
    }
}

// W2: [4096 lh][1024 o] -> w2c[o][p32(lh)] fp16
__global__ void k_prep_w2(const float* __restrict__ w2s) {
    int bid = blockIdx.x;
    int k0 = (bid >> 5) * 32;
    int o0 = (bid & 31) * 32;
    __shared__ float ts[32][33];
    int tid = threadIdx.x;
    int ki = tid >> 3, oj = (tid & 7) * 4;
    float4 v = *(const float4*)(w2s + (size_t)(k0 + ki) * OUTF + o0 + oj);
    ts[oj + 0][ki] = v.x; ts[oj + 1][ki] = v.y;
    ts[oj + 2][ki] = v.z; ts[oj + 3][ki] = v.w;
    __syncthreads();
    int oi = tid >> 3, kj = (tid & 7) * 4;
    size_t drow = (size_t)(o0 + oi) * APITCH;
#pragma unroll
    for (int e = 0; e < 4; e++)
        g_w2c[drow + p32(k0 + kj + e)] = __float2half(ts[oi][kj + e]);
}

__global__ void k_prep_tail(const float* __restrict__ b2s) {  // w2c bias+zero cols
    int idx = blockIdx.x * 256 + threadIdx.x;    // 1024 * 64
    int o = idx >> 6, c = idx & 63;
    float v = 0.f;
    if (c < 32) {
        int l = p32(c);
        if (l < 16) v = b2s[l * OUTF + o];
    }
    g_w2c[(size_t)o * APITCH + ACOLS + c] = __float2half(v);
}

// ---------------------------------------------------------------------------
// Node logits
// ---------------------------------------------------------------------------
__global__ void k_logits(const float* __restrict__ x,
                         const float* __restrict__ nw,
                         const float* __restrict__ nb) {
    __shared__ float xs[128][33];
    __shared__ float ws[16][33];
    const int tid = threadIdx.x;
    const int row0 = blockIdx.x * 128;
    const int node = tid & 15;
    const int rg = tid >> 4;
    float acc[8];
#pragma unroll
    for (int j = 0; j < 8; j++) acc[j] = 0.f;
    for (int k0 = 0; k0 < INF; k0 += 32) {
#pragma unroll
        for (int i = 0; i < 16; i++) {
            int idx = tid + 256 * i;
            int r = idx >> 5, c = idx & 31;
            xs[r][c] = x[(size_t)(row0 + r) * INF + k0 + c];
        }
        for (int idx = tid; idx < 512; idx += 256) {
            int r = idx >> 5, c = idx & 31;
            ws[r][c] = (r < NNODE) ? nw[(size_t)r * INF + k0 + c] : 0.f;
        }
        __syncthreads();
#pragma unroll
        for (int k = 0; k < 32; k++) {
            float wv = ws[node][k];
#pragma unroll
            for (int j = 0; j < 8; j++) acc[j] += xs[rg + 16 * j][k] * wv;
        }
        __syncthreads();
    }
    float bias = (node < NNODE) ? nb[node] : 0.f;
#pragma unroll
    for (int j = 0; j < 8; j++)
        g_logits[(size_t)(row0 + rg + 16 * j) * 16 + node] = acc[j] + bias;
}

// Fused: blocks [0,512) mixture; blocks [512,528) b1 permute.
__global__ void k_mix_b1(const float* __restrict__ b1s) {
    int tid = threadIdx.x;
    if (blockIdx.x < 512) {
        int idx = blockIdx.x * 256 + tid;
        int b = idx >> 4, l = idx & 15;
        float m = 1.f;
#pragma unroll
        for (int d = 0; d < 4; d++) {
            int g = l >> (3 - d);
            int node = (1 << d) - 1 + (g >> 1);
            float z = g_logits[(size_t)b * 16 + node];
            float s = 1.f / (1.f + expf(-z));
            m *= (g & 1) ? s : (1.f - s);
        }
        g_mix[idx] = m;
        __half* arow = g_A + (size_t)b * APITCH + ACOLS;
        arow[p32(l)]      = __float2half(m);       // mixture at phys col p32(l)
        arow[p32(l + 16)] = __float2half(0.f);     // zeros in first 32-block
        arow[32 + 2 * l]     = __float2half(0.f);  // pad block 4128..4159
        arow[32 + 2 * l + 1] = __float2half(0.f);
    } else {
        int p = (blockIdx.x - 512) * 256 + tid;    // < 4096
        g_b1c[p] = b1s[p32(p)];
    }
}

// ---------------------------------------------------------------------------
// FP16 HMMA GEMM (fp32 accum): block 128x128, 128 threads / 4 warps (2x2),
// warp tile 64x64, k-tile 64 (two 32-sub-tiles), THREE-stage cp.async
// (wait_group 1 in steady state -> loads stay in flight through compute),
// one __syncthreads per k-tile, 2 CTAs/SM, 96KB smem.
// MODE 0: g_A(phys cols) = fp16(mix * relu(x@W1 + b1))   K=1024
// MODE 1: out = g_A @ w2c^T                              K=4160 (bias in K)
// ---------------------------------------------------------------------------
#define NSTG 3
#define STGH 16384      // halfs per stage: Asub0|Asub1|Bsub0|Bsub1, 4096 each

template <int MODE>
__global__ __launch_bounds__(128, 2) void k_gemm(float* __restrict__ Cg) {
    extern __shared__ __half sm[];
    constexpr int K   = MODE ? APITCH : INF;
    constexpr int NKT = K / 64;

    const int tid  = threadIdx.x;
    const int lane = tid & 31;
    const int warp = tid >> 5;               // 0..3
    const int wm = (warp & 1) * 64;
    const int wn = (warp >> 1) * 64;
    const int m0 = blockIdx.y * 128;
    const int n0 = blockIdx.x * 128;

    const __half* Ap = (MODE ? g_A : g_xc) + (size_t)m0 * K;
    const __half* Bp = (MODE ? g_w2c : g_w1c) + (size_t)n0 * K;

    float acc[4][8][4];
#pragma unroll
    for (int a = 0; a < 4; a++)
#pragma unroll
        for (int b = 0; b < 8; b++)
#pragma unroll
            for (int e = 0; e < 4; e++) acc[a][b][e] = 0.f;

    auto load_stage = [&](int kt, int stg) {
        __half* S = sm + stg * STGH;
#pragma unroll
        for (int sub = 0; sub < 2; sub++) {
            const int kb = kt * 64 + sub * 32;
#pragma unroll
            for (int i = 0; i < 4; i++) {
                int id = tid + 128 * i;          // 0..511
                int r = id >> 2, c = (id & 3) * 8;
                cpasync16(S + sub * 4096 + r * 32 + c, Ap + (size_t)r * K + kb + c);
                cpasync16(S + 8192 + sub * 4096 + r * 32 + c, Bp + (size_t)r * K + kb + c);
            }
        }
        asm volatile("cp.async.commit_group;\n");
    };

    load_stage(0, 0);
    load_stage(1, 1);

#pragma unroll 1
    for (int kt = 0; kt < NKT; kt++) {
        // need stage kt%3 complete; outstanding groups are at most {kt, kt+1}
        if (kt + 1 < NKT) asm volatile("cp.async.wait_group 1;\n");
        else              asm volatile("cp.async.wait_group 0;\n");
        __syncthreads();
        if (kt + 2 < NKT) load_stage(kt + 2, (kt + 2) % NSTG);

        const __half* S = sm + (kt % NSTG) * STGH;
#pragma unroll
        for (int sub = 0; sub < 2; sub++) {
            const __half* Asub = S + sub * 4096;
            const __half* Bsub = S + 8192 + sub * 4096;
            uint4 a0v[4], a1v[4], bv[8];
#pragma unroll
            for (int mt = 0; mt < 4; mt++) {
                int r = wm + mt * 16 + (lane >> 2);
                a0v[mt] = *(const uint4*)(Asub + r * 32 + (lane & 3) * 8);
                a1v[mt] = *(const uint4*)(Asub + (r + 8) * 32 + (lane & 3) * 8);
            }
#pragma unroll
            for (int nt = 0; nt < 8; nt++) {
                int n = wn + nt * 8 + (lane >> 2);
                bv[nt] = *(const uint4*)(Bsub + n * 32 + (lane & 3) * 8);
            }
            // step 0: k 0..15 of sub-tile
#pragma unroll
            for (int mt = 0; mt < 4; mt++)
#pragma unroll
                for (int nt = 0; nt < 8; nt++)
                    mma_f16(acc[mt][nt], a0v[mt].x, a1v[mt].x, a0v[mt].y, a1v[mt].y,
                            bv[nt].x, bv[nt].y);
            // step 1: k 16..31
#pragma unroll
            for (int mt = 0; mt < 4; mt++)
#pragma unroll
                for (int nt = 0; nt < 8; nt++)
                    mma_f16(acc[mt][nt], a0v[mt].z, a1v[mt].z, a0v[mt].w, a1v[mt].w,
                            bv[nt].z, bv[nt].w);
        }
        // stage (kt+2)%3 written above was last read in compute kt-1, which
        // all warps finished before this iteration's barrier.
    }

    // epilogue
    if (MODE == 0) {
        const int l = n0 >> 8;       // leaf constant per block
#pragma unroll
        for (int mt = 0; mt < 4; mt++) {
#pragma unroll
            for (int half_ = 0; half_ < 2; half_++) {
                int gm = m0 + wm + mt * 16 + (lane >> 2) + half_ * 8;
                float mx = g_mix[(size_t)gm * 16 + l];
                __half* arow = g_A + (size_t)gm * APITCH;
#pragma unroll
                for (int nt = 0; nt < 8; nt++) {
                    int gn = n0 + wn + nt * 8 + 2 * (lane & 3);
                    float v0 = fmaxf(acc[mt][nt][2 * half_ + 0] + g_b1c[gn], 0.f) * mx;
                    float v1 = fmaxf(acc[mt][nt][2 * half_ + 1] + g_b1c[gn + 1], 0.f) * mx;
                    *(half2*)(arow + gn) = __floats2half2_rn(v0, v1);
                }
            }
        }
    } else {
#pragma unroll
        for (int mt = 0; mt < 4; mt++) {
#pragma unroll
            for (int half_ = 0; half_ < 2; half_++) {
                int gm = m0 + wm + mt * 16 + (lane >> 2) + half_ * 8;
#pragma unroll
                for (int nt = 0; nt < 8; nt++) {
                    int gn = n0 + wn + nt * 8 + 2 * (lane & 3);
                    *(float2*)(Cg + (size_t)gm * OUTF + gn) =
                        make_float2(acc[mt][nt][2 * half_ + 0], acc[mt][nt][2 * half_ + 1]);
                }
            }
        }
    }
}

// ---------------------------------------------------------------------------
extern "C" void kernel_launch(void* const* d_in, const int* in_sizes, int n_in,
                              void* d_out, int out_size) {
    const float* x   = (const float*)d_in[0];
    const float* nw  = (const float*)d_in[1];
    const float* nb  = (const float*)d_in[2];
    const float* w1s = (const float*)d_in[3];
    const float* b1s = (const float*)d_in[4];
    const float* w2s = (const float*)d_in[5];
    const float* b2s = (const float*)d_in[6];
    float* out = (float*)d_out;

    const int SMEM = NSTG * STGH * 2;   // 96 KB
    cudaFuncSetAttribute(k_gemm<0>, cudaFuncAttributeMaxDynamicSharedMemorySize, SMEM);
    cudaFuncSetAttribute(k_gemm<1>, cudaFuncAttributeMaxDynamicSharedMemorySize, SMEM);

    // gemm<0> is the 4th launch -> lands in ncu's capture window.
    k_logits   <<<BATCH / 128, 256>>>(x, nw, nb);
    k_prep_a   <<<16384 + 4096, 256>>>(x, w1s);
    k_mix_b1   <<<512 + 16, 256>>>(b1s);
    k_gemm<0>  <<<dim3(ACOLS / 128, BATCH / 128), 128, SMEM>>>(nullptr);
    k_prep_w2  <<<4096, 256>>>(w2s);
    k_prep_tail<<<1024 * 64 / 256, 256>>>(b2s);
    k_gemm<1>  <<<dim3(OUTF / 128, BATCH / 128), 128, SMEM>>>(out);
}